// round 14
// baseline (speedup 1.0000x reference)
#include <cuda_runtime.h>

// GAE: advantages/targets, B=4096 rows, T=8192 timesteps.
// delta_t = r_t + GAMMA*v_{t+1} - v_t ; A_t = delta_t + COEF*A_{t+1}
// targets_t = v_t + A_t. Output: [advantages | targets] float32.
//
// R14 = champion config (R7/R12/R13: truncated-window parallel GAE,
// COEF^512 ~ 2e-14 -> each 4096-chunk independent given a 512-elem halo;
// 2 CTAs/row, 512 thr, 4 CTAs/SM; quad-register LDG.128/STG.128 with values
// realigned via compile-time O=row%4; constant-multiplier shuffle scans)
// plus: v for this chunk is stashed in padded smem during phase 1 (16.5 KB/CTA,
// occupancy preserved) so phase 3 does ZERO global loads — tests whether the
// phase-3 v re-read was falling out of L1 to L2.

constexpr int   B_CONST = 4096;
constexpr int   T_CONST = 8192;
constexpr float GAMMA   = 0.99f;
constexpr float COEF    = 0.99f * 0.95f;
constexpr int   THREADS = 512;
constexpr int   CHUNK   = 4096;                 // per-CTA main window
constexpr int   NITER   = CHUNK / (4 * THREADS);// 2 quad iterations
constexpr int   NMAIN   = 32;                   // 128-elem warp-chunks per CTA
constexpr int   NHALO   = 16;                   // 32-elem halo warp-chunks
constexpr int   VPAD    = CHUNK + (CHUNK / 128) * 4;  // 4224 floats, 16.5 KB

// padded v-cache index: +1 float4 per 128 floats; keeps 16B alignment
// (x % 4 == 0 -> pv(x) % 4 == 0) and rotates banks across 128-elem blocks.
__device__ __forceinline__ int pv(int x) { return x + ((x >> 7) << 2); }

__device__ __forceinline__ float powi_coef(float base, int n) {
    float r = 1.0f, b = base;
    #pragma unroll
    for (int bit = 0; bit < 7; ++bit) {        // n < 128
        if (n & (1 << bit)) r *= b;
        b *= b;
    }
    return r;
}

// scan constants
#define C1  (COEF)
#define C2  (C1*C1)
#define C3  (C2*C1)
#define C4  (C2*C2)
#define C8  (C4*C4)
#define C16 (C8*C8)
#define C32 (C16*C16)
#define C64 (C32*C32)
#define M32  C32
#define M128 (C64*C64)

template<int O>
__device__ __forceinline__ void gae_body(const float* __restrict__ r_row,
                                         const float* __restrict__ v_row,
                                         float* __restrict__ arow,
                                         float* __restrict__ trow,
                                         int cbase,
                                         float* __restrict__ V,      // [VPAD]
                                         float* __restrict__ sum,    // [48]
                                         float* __restrict__ csum)   // [32]
{
    const int tid  = threadIdx.x;
    const int lane = tid & 31;
    const int wid  = tid >> 5;
    const bool has_halo = (cbase + CHUNK) < T_CONST;   // uniform across CTA

    float s0[NITER], s1[NITER], s2[NITER], s3[NITER];

    // ── Phase 1: main quads. Load, stash v in smem, delta, quad scan, warp scan.
    #pragma unroll
    for (int i = 0; i < NITER; ++i) {
        const int t4 = cbase + 4 * (tid + i * THREADS);
        // v[t4..t4+4] from two aligned float4s (window select is compile-time)
        float4 lo = __ldg(reinterpret_cast<const float4*>(v_row + t4 - O));
        float4 hi = __ldg(reinterpret_cast<const float4*>(v_row + t4 - O + 4));
        float w[8] = {lo.x, lo.y, lo.z, lo.w, hi.x, hi.y, hi.z, hi.w};
        float4 r4 = __ldg(reinterpret_cast<const float4*>(r_row + t4));

        // stash v_t quad for phase 3 (STS.128, conflict-free)
        *reinterpret_cast<float4*>(V + pv(t4 - cbase)) =
            make_float4(w[O], w[O + 1], w[O + 2], w[O + 3]);

        float d0 = r4.x + GAMMA * w[O + 1] - w[O];
        float d1 = r4.y + GAMMA * w[O + 2] - w[O + 1];
        float d2 = r4.z + GAMMA * w[O + 3] - w[O + 2];
        float d3 = r4.w + GAMMA * w[O + 4] - w[O + 3];

        // reverse scan within quad (zero carry)
        float q3 = d3;
        float q2 = fmaf(C1, q3, d2);
        float q1 = fmaf(C1, q2, d1);
        float q0 = fmaf(C1, q1, d0);

        // warp reverse scan of quad summaries, multiplier C4 per step
        float S = q0, a2;
        a2 = __shfl_down_sync(0xffffffffu, S, 1);  if (lane < 31) S = fmaf(C4,  a2, S);
        a2 = __shfl_down_sync(0xffffffffu, S, 2);  if (lane < 30) S = fmaf(C8,  a2, S);
        a2 = __shfl_down_sync(0xffffffffu, S, 4);  if (lane < 28) S = fmaf(C16, a2, S);
        a2 = __shfl_down_sync(0xffffffffu, S, 8);  if (lane < 24) S = fmaf(C32, a2, S);
        a2 = __shfl_down_sync(0xffffffffu, S, 16); if (lane < 16) S = fmaf(C64, a2, S);

        float E = __shfl_down_sync(0xffffffffu, S, 1);   // carry into this quad
        if (lane == 31) E = 0.0f;

        s0[i] = fmaf(C4, E, q0);
        s1[i] = fmaf(C3, E, q1);
        s2[i] = fmaf(C2, E, q2);
        s3[i] = fmaf(C1, E, q3);
        if (lane == 0) sum[i * 16 + wid] = S;    // 128-elem chunk summary
    }

    // ── Halo pass: 512 scalar elements beyond the chunk. Uniform branch:
    // second-half CTAs have no in-bounds halo and skip the work entirely.
    if (has_halo) {
        const int t = cbase + CHUNK + tid;
        float vt  = __ldg(v_row + t);
        float vt1 = __ldg(v_row + t + 1);
        float rt  = __ldg(r_row + t);
        float a = rt + GAMMA * vt1 - vt;
        float a2;
        a2 = __shfl_down_sync(0xffffffffu, a, 1);  if (lane < 31) a = fmaf(C1,  a2, a);
        a2 = __shfl_down_sync(0xffffffffu, a, 2);  if (lane < 30) a = fmaf(C2,  a2, a);
        a2 = __shfl_down_sync(0xffffffffu, a, 4);  if (lane < 28) a = fmaf(C4,  a2, a);
        a2 = __shfl_down_sync(0xffffffffu, a, 8);  if (lane < 24) a = fmaf(C8,  a2, a);
        a2 = __shfl_down_sync(0xffffffffu, a, 16); if (lane < 16) a = fmaf(C16, a2, a);
        if (lane == 0) sum[NMAIN + wid] = a;     // 32-elem halo chunk summary
    } else if (tid < NHALO) {
        sum[NMAIN + tid] = 0.0f;
    }
    __syncthreads();

    // ── Phase 2 (warp 0 only): scan 16 halo summaries (mult M32), then 32
    // main summaries (mult M128); fold halo total in analytically.
    if (wid == 0) {
        float A = (lane < NHALO) ? sum[NMAIN + lane] : 0.0f;
        float a2, k = M32;
        a2 = __shfl_down_sync(0xffffffffu, A, 1);  if (lane < 31) A = fmaf(k, a2, A); k *= k;
        a2 = __shfl_down_sync(0xffffffffu, A, 2);  if (lane < 30) A = fmaf(k, a2, A); k *= k;
        a2 = __shfl_down_sync(0xffffffffu, A, 4);  if (lane < 28) A = fmaf(k, a2, A); k *= k;
        a2 = __shfl_down_sync(0xffffffffu, A, 8);  if (lane < 24) A = fmaf(k, a2, A);
        float T1 = __shfl_sync(0xffffffffu, A, 0);

        // main scan (zero carry), uniform multiplier M128
        float S = sum[lane];
        k = M128;
        a2 = __shfl_down_sync(0xffffffffu, S, 1);  if (lane < 31) S = fmaf(k, a2, S); k *= k;
        a2 = __shfl_down_sync(0xffffffffu, S, 2);  if (lane < 30) S = fmaf(k, a2, S); k *= k;
        a2 = __shfl_down_sync(0xffffffffu, S, 4);  if (lane < 28) S = fmaf(k, a2, S); k *= k;
        a2 = __shfl_down_sync(0xffffffffu, S, 8);  if (lane < 24) S = fmaf(k, a2, S); k *= k;
        a2 = __shfl_down_sync(0xffffffffu, S, 16); if (lane < 16) S = fmaf(k, a2, S);

        // carry entering chunk c: G_{c+1} = S_{c+1} + M128^(31-c) * T1
        float Sn   = __shfl_down_sync(0xffffffffu, S, 1);
        float corr = powi_coef(M128, 31 - lane);
        csum[lane] = (lane == 31) ? T1 : fmaf(corr, T1, Sn);
    }
    __syncthreads();

    // ── Phase 3: apply carries; v from smem (LDS.128); vector global stores.
    float m3 = powi_coef(COEF, 125 - 4 * lane);           // COEF^(125-4l)
    float m2 = m3 * C1, m1 = m2 * C1, m0 = m1 * C1;       // up to COEF^(128-4l)

    #pragma unroll
    for (int i = 0; i < NITER; ++i) {
        const int t4 = cbase + 4 * (tid + i * THREADS);
        const float carry = csum[i * 16 + wid];           // broadcast in warp
        float A0 = fmaf(m0, carry, s0[i]);
        float A1 = fmaf(m1, carry, s1[i]);
        float A2 = fmaf(m2, carry, s2[i]);
        float A3 = fmaf(m3, carry, s3[i]);

        float4 v4 = *reinterpret_cast<const float4*>(V + pv(t4 - cbase));

        *reinterpret_cast<float4*>(arow + t4) = make_float4(A0, A1, A2, A3);
        *reinterpret_cast<float4*>(trow + t4) =
            make_float4(v4.x + A0, v4.y + A1, v4.z + A2, v4.w + A3);
    }
}

__global__ __launch_bounds__(THREADS, 4)
void gae_kernel(const float* __restrict__ rewards,
                const float* __restrict__ values,
                float* __restrict__ adv_out,
                float* __restrict__ tgt_out)
{
    extern __shared__ float V[];           // VPAD floats: v_t cache
    __shared__ float sum[NMAIN + NHALO];   // 48 chunk summaries
    __shared__ float csum[NMAIN];          // carries for main chunks

    const int row   = blockIdx.x >> 1;
    const int half  = blockIdx.x & 1;
    const int cbase = half * CHUNK;

    const float* r_row = rewards + (size_t)row * T_CONST;
    const float* v_row = values  + (size_t)row * (T_CONST + 1);
    float* arow = adv_out + (size_t)row * T_CONST;
    float* trow = tgt_out + (size_t)row * T_CONST;

    // values row misalignment: O = (row*8193 + t) % 4 = row % 4 for 4|t.
    // Last row (4095) has O=3 -> max vector-touched index is exactly v[T].
    // Other rows may over-read <=3 floats into the next row: inside buffer.
    switch (row & 3) {
        case 0:  gae_body<0>(r_row, v_row, arow, trow, cbase, V, sum, csum); break;
        case 1:  gae_body<1>(r_row, v_row, arow, trow, cbase, V, sum, csum); break;
        case 2:  gae_body<2>(r_row, v_row, arow, trow, cbase, V, sum, csum); break;
        default: gae_body<3>(r_row, v_row, arow, trow, cbase, V, sum, csum); break;
    }
}

extern "C" void kernel_launch(void* const* d_in, const int* in_sizes, int n_in,
                              void* d_out, int out_size)
{
    const float* rewards = (const float*)d_in[0];   // [B, T]
    const float* values  = (const float*)d_in[1];   // [B, T+1]
    float* adv = (float*)d_out;                     // [B, T]
    float* tgt = adv + (size_t)B_CONST * T_CONST;   // [B, T]

    const int smem_bytes = VPAD * (int)sizeof(float);  // ~16.5 KB per CTA
    cudaFuncSetAttribute(gae_kernel, cudaFuncAttributeMaxDynamicSharedMemorySize, smem_bytes);

    gae_kernel<<<B_CONST * 2, THREADS, smem_bytes>>>(rewards, values, adv, tgt);
}

// round 15
// speedup vs baseline: 1.0499x; 1.0499x over previous
#include <cuda_runtime.h>

// GAE: advantages/targets, B=4096 rows, T=8192 timesteps.
// delta_t = r_t + GAMMA*v_{t+1} - v_t ; A_t = delta_t + COEF*A_{t+1}
// targets_t = v_t + A_t. Output: [advantages | targets] float32.
//
// FINAL (= R7 champion, triple-reproduced at 82.2-82.7us wall, ~6.35 TB/s =
// ~80% of HBM spec at compulsory-only traffic):
// Truncated-window parallel GAE. COEF^512 ~ 2e-14, so each 4096-chunk is
// computed independently with a 512-element halo (error <<< 1e-3 tolerance).
// 2 CTAs/row, 512 thr, 8 main elems + 1 halo elem per thread -> 32 regs,
// 4 CTAs/SM. Quad-register layout: LDG.128/STG.128 everywhere (values
// realigned via compile-time O = row%4 template). Constant-multiplier
// shuffle scans; warp0 scans 48 chunk summaries; 2 barriers total.
// Falsified alternatives: finer grain (R8), cache hints (R9), no-halo
// full-row (R10), divergent/reordered halo (R11/R13), smem v-cache (R4/R14).

constexpr int   B_CONST = 4096;
constexpr int   T_CONST = 8192;
constexpr float GAMMA   = 0.99f;
constexpr float COEF    = 0.99f * 0.95f;
constexpr int   THREADS = 512;
constexpr int   CHUNK   = 4096;                 // per-CTA main window
constexpr int   NITER   = CHUNK / (4 * THREADS);// 2 quad iterations
constexpr int   NMAIN   = 32;                   // 128-elem warp-chunks per CTA
constexpr int   NHALO   = 16;                   // 32-elem halo warp-chunks

__device__ __forceinline__ float powi_coef(float base, int n) {
    float r = 1.0f, b = base;
    #pragma unroll
    for (int bit = 0; bit < 7; ++bit) {        // n < 128
        if (n & (1 << bit)) r *= b;
        b *= b;
    }
    return r;
}

// scan constants
#define C1  (COEF)
#define C2  (C1*C1)
#define C3  (C2*C1)
#define C4  (C2*C2)
#define C8  (C4*C4)
#define C16 (C8*C8)
#define C32 (C16*C16)
#define C64 (C32*C32)
#define M32  C32
#define M128 (C64*C64)

template<int O>
__device__ __forceinline__ void gae_body(const float* __restrict__ r_row,
                                         const float* __restrict__ v_row,
                                         float* __restrict__ arow,
                                         float* __restrict__ trow,
                                         int cbase,
                                         float* __restrict__ sum,    // [48]
                                         float* __restrict__ csum)   // [32]
{
    const int tid  = threadIdx.x;
    const int lane = tid & 31;
    const int wid  = tid >> 5;

    float s0[NITER], s1[NITER], s2[NITER], s3[NITER];

    // ── Phase 1: main quads. Load, delta, quad scan, warp scan (mult C4^d).
    #pragma unroll
    for (int i = 0; i < NITER; ++i) {
        const int t4 = cbase + 4 * (tid + i * THREADS);
        // v[t4..t4+4] from two aligned float4s (window select is compile-time)
        float4 lo = __ldg(reinterpret_cast<const float4*>(v_row + t4 - O));
        float4 hi = __ldg(reinterpret_cast<const float4*>(v_row + t4 - O + 4));
        float w[8] = {lo.x, lo.y, lo.z, lo.w, hi.x, hi.y, hi.z, hi.w};
        float4 r4 = __ldg(reinterpret_cast<const float4*>(r_row + t4));

        float d0 = r4.x + GAMMA * w[O + 1] - w[O];
        float d1 = r4.y + GAMMA * w[O + 2] - w[O + 1];
        float d2 = r4.z + GAMMA * w[O + 3] - w[O + 2];
        float d3 = r4.w + GAMMA * w[O + 4] - w[O + 3];

        // reverse scan within quad (zero carry)
        float q3 = d3;
        float q2 = fmaf(C1, q3, d2);
        float q1 = fmaf(C1, q2, d1);
        float q0 = fmaf(C1, q1, d0);

        // warp reverse scan of quad summaries, multiplier C4 per step
        float S = q0, a2;
        a2 = __shfl_down_sync(0xffffffffu, S, 1);  if (lane < 31) S = fmaf(C4,  a2, S);
        a2 = __shfl_down_sync(0xffffffffu, S, 2);  if (lane < 30) S = fmaf(C8,  a2, S);
        a2 = __shfl_down_sync(0xffffffffu, S, 4);  if (lane < 28) S = fmaf(C16, a2, S);
        a2 = __shfl_down_sync(0xffffffffu, S, 8);  if (lane < 24) S = fmaf(C32, a2, S);
        a2 = __shfl_down_sync(0xffffffffu, S, 16); if (lane < 16) S = fmaf(C64, a2, S);

        float E = __shfl_down_sync(0xffffffffu, S, 1);   // carry into this quad
        if (lane == 31) E = 0.0f;

        s0[i] = fmaf(C4, E, q0);
        s1[i] = fmaf(C3, E, q1);
        s2[i] = fmaf(C2, E, q2);
        s3[i] = fmaf(C1, E, q3);
        if (lane == 0) sum[i * 16 + wid] = S;    // 128-elem chunk summary
    }

    // ── Halo pass: 512 scalar elements beyond the chunk (guarded at row end).
    {
        const int t = cbase + CHUNK + tid;
        const bool inb = (t < T_CONST);
        float vt  = inb ? __ldg(v_row + t)     : 0.0f;
        float vt1 = inb ? __ldg(v_row + t + 1) : 0.0f;
        float rt  = inb ? __ldg(r_row + t)     : 0.0f;
        float a = inb ? (rt + GAMMA * vt1 - vt) : 0.0f;
        float a2;
        a2 = __shfl_down_sync(0xffffffffu, a, 1);  if (lane < 31) a = fmaf(C1,  a2, a);
        a2 = __shfl_down_sync(0xffffffffu, a, 2);  if (lane < 30) a = fmaf(C2,  a2, a);
        a2 = __shfl_down_sync(0xffffffffu, a, 4);  if (lane < 28) a = fmaf(C4,  a2, a);
        a2 = __shfl_down_sync(0xffffffffu, a, 8);  if (lane < 24) a = fmaf(C8,  a2, a);
        a2 = __shfl_down_sync(0xffffffffu, a, 16); if (lane < 16) a = fmaf(C16, a2, a);
        if (lane == 0) sum[NMAIN + wid] = a;     // 32-elem halo chunk summary
    }
    __syncthreads();

    // ── Phase 2 (warp 0 only): scan 16 halo summaries (mult M32), then 32
    // main summaries (mult M128); fold halo total in analytically.
    if (wid == 0) {
        float A = (lane < NHALO) ? sum[NMAIN + lane] : 0.0f;
        float a2, k = M32;
        a2 = __shfl_down_sync(0xffffffffu, A, 1);  if (lane < 31) A = fmaf(k, a2, A); k *= k;
        a2 = __shfl_down_sync(0xffffffffu, A, 2);  if (lane < 30) A = fmaf(k, a2, A); k *= k;
        a2 = __shfl_down_sync(0xffffffffu, A, 4);  if (lane < 28) A = fmaf(k, a2, A); k *= k;
        a2 = __shfl_down_sync(0xffffffffu, A, 8);  if (lane < 24) A = fmaf(k, a2, A);
        float T1 = __shfl_sync(0xffffffffu, A, 0);

        // main scan (zero carry), uniform multiplier M128
        float S = sum[lane];
        k = M128;
        a2 = __shfl_down_sync(0xffffffffu, S, 1);  if (lane < 31) S = fmaf(k, a2, S); k *= k;
        a2 = __shfl_down_sync(0xffffffffu, S, 2);  if (lane < 30) S = fmaf(k, a2, S); k *= k;
        a2 = __shfl_down_sync(0xffffffffu, S, 4);  if (lane < 28) S = fmaf(k, a2, S); k *= k;
        a2 = __shfl_down_sync(0xffffffffu, S, 8);  if (lane < 24) S = fmaf(k, a2, S); k *= k;
        a2 = __shfl_down_sync(0xffffffffu, S, 16); if (lane < 16) S = fmaf(k, a2, S);

        // carry entering chunk c: G_{c+1} = S_{c+1} + M128^(31-c) * T1
        float Sn   = __shfl_down_sync(0xffffffffu, S, 1);
        float corr = powi_coef(M128, 31 - lane);
        csum[lane] = (lane == 31) ? T1 : fmaf(corr, T1, Sn);
    }
    __syncthreads();

    // ── Phase 3: apply carries, reload v (L1/L2-resident), vector stores.
    float m3 = powi_coef(COEF, 125 - 4 * lane);           // COEF^(125-4l)
    float m2 = m3 * C1, m1 = m2 * C1, m0 = m1 * C1;       // .. up to COEF^(128-4l)

    #pragma unroll
    for (int i = 0; i < NITER; ++i) {
        const int t4 = cbase + 4 * (tid + i * THREADS);
        const float carry = csum[i * 16 + wid];           // broadcast in warp
        float A0 = fmaf(m0, carry, s0[i]);
        float A1 = fmaf(m1, carry, s1[i]);
        float A2 = fmaf(m2, carry, s2[i]);
        float A3 = fmaf(m3, carry, s3[i]);

        float w0, w1, w2, w3;
        {
            float4 lo = __ldg(reinterpret_cast<const float4*>(v_row + t4 - O));
            if constexpr (O == 0) {
                w0 = lo.x; w1 = lo.y; w2 = lo.z; w3 = lo.w;
            } else {
                float4 hi = __ldg(reinterpret_cast<const float4*>(v_row + t4 - O + 4));
                float w[8] = {lo.x, lo.y, lo.z, lo.w, hi.x, hi.y, hi.z, hi.w};
                w0 = w[O]; w1 = w[O + 1]; w2 = w[O + 2]; w3 = w[O + 3];
            }
        }
        *reinterpret_cast<float4*>(arow + t4) = make_float4(A0, A1, A2, A3);
        *reinterpret_cast<float4*>(trow + t4) =
            make_float4(w0 + A0, w1 + A1, w2 + A2, w3 + A3);
    }
}

__global__ __launch_bounds__(THREADS, 4)
void gae_kernel(const float* __restrict__ rewards,
                const float* __restrict__ values,
                float* __restrict__ adv_out,
                float* __restrict__ tgt_out)
{
    __shared__ float sum[NMAIN + NHALO];   // 48 chunk summaries
    __shared__ float csum[NMAIN];          // carries for main chunks

    const int row   = blockIdx.x >> 1;
    const int half  = blockIdx.x & 1;
    const int cbase = half * CHUNK;

    const float* r_row = rewards + (size_t)row * T_CONST;
    const float* v_row = values  + (size_t)row * (T_CONST + 1);
    float* arow = adv_out + (size_t)row * T_CONST;
    float* trow = tgt_out + (size_t)row * T_CONST;

    // values row misalignment: O = (row*8193 + t) % 4 = row % 4 for 4|t.
    // Last row (4095) has O=3 -> max vector-touched index is exactly v[T].
    // Other rows may over-read <=3 floats into the next row: inside buffer.
    switch (row & 3) {
        case 0:  gae_body<0>(r_row, v_row, arow, trow, cbase, sum, csum); break;
        case 1:  gae_body<1>(r_row, v_row, arow, trow, cbase, sum, csum); break;
        case 2:  gae_body<2>(r_row, v_row, arow, trow, cbase, sum, csum); break;
        default: gae_body<3>(r_row, v_row, arow, trow, cbase, sum, csum); break;
    }
}

extern "C" void kernel_launch(void* const* d_in, const int* in_sizes, int n_in,
                              void* d_out, int out_size)
{
    const float* rewards = (const float*)d_in[0];   // [B, T]
    const float* values  = (const float*)d_in[1];   // [B, T+1]
    float* adv = (float*)d_out;                     // [B, T]
    float* tgt = adv + (size_t)B_CONST * T_CONST;   // [B, T]

    gae_kernel<<<B_CONST * 2, THREADS>>>(rewards, values, adv, tgt);
}

// round 16
// speedup vs baseline: 1.0544x; 1.0043x over previous
#include <cuda_runtime.h>

// GAE: advantages/targets, B=4096 rows, T=8192 timesteps.
// delta_t = r_t + GAMMA*v_{t+1} - v_t ; A_t = delta_t + COEF*A_{t+1}
// targets_t = v_t + A_t. Output: [advantages | targets] float32.
//
// TERMINAL KERNEL (champion, 4x reproduced: 82.2-82.7us wall; kernel 74.4us
// at 6.47 TB/s = 81% of HBM spec with compulsory-only traffic):
// Truncated-window parallel GAE. COEF^512 ~ 2e-14, so each 4096-chunk is
// computed independently with a 512-element halo (error <<< 1e-3 tolerance).
// 2 CTAs/row, 512 thr, 8 main elems + 1 halo elem per thread -> 32 regs,
// 4 CTAs/SM (64 warps). Quad-register layout: LDG.128/STG.128 everywhere
// (values rows are 4B-misaligned; realigned via compile-time O = row%4
// template). Constant-multiplier shuffle scans (uniform-coefficient trick:
// a += COEF^d * shfl_down(a,d)); warp0 scans 48 chunk summaries; 2 barriers.
// Falsified alternatives: smem data staging (R2-R4, R14), scalar coalesced
// loads (R3), finer CTA grain (R8), cache hints __ldcs/__stcs (R9), no-halo
// full-row 1024thr (R10), divergent/reordered halo (R11, R13).

constexpr int   B_CONST = 4096;
constexpr int   T_CONST = 8192;
constexpr float GAMMA   = 0.99f;
constexpr float COEF    = 0.99f * 0.95f;
constexpr int   THREADS = 512;
constexpr int   CHUNK   = 4096;                 // per-CTA main window
constexpr int   NITER   = CHUNK / (4 * THREADS);// 2 quad iterations
constexpr int   NMAIN   = 32;                   // 128-elem warp-chunks per CTA
constexpr int   NHALO   = 16;                   // 32-elem halo warp-chunks

__device__ __forceinline__ float powi_coef(float base, int n) {
    float r = 1.0f, b = base;
    #pragma unroll
    for (int bit = 0; bit < 7; ++bit) {        // n < 128
        if (n & (1 << bit)) r *= b;
        b *= b;
    }
    return r;
}

// scan constants
#define C1  (COEF)
#define C2  (C1*C1)
#define C3  (C2*C1)
#define C4  (C2*C2)
#define C8  (C4*C4)
#define C16 (C8*C8)
#define C32 (C16*C16)
#define C64 (C32*C32)
#define M32  C32
#define M128 (C64*C64)

template<int O>
__device__ __forceinline__ void gae_body(const float* __restrict__ r_row,
                                         const float* __restrict__ v_row,
                                         float* __restrict__ arow,
                                         float* __restrict__ trow,
                                         int cbase,
                                         float* __restrict__ sum,    // [48]
                                         float* __restrict__ csum)   // [32]
{
    const int tid  = threadIdx.x;
    const int lane = tid & 31;
    const int wid  = tid >> 5;

    float s0[NITER], s1[NITER], s2[NITER], s3[NITER];

    // ── Phase 1: main quads. Load, delta, quad scan, warp scan (mult C4^d).
    #pragma unroll
    for (int i = 0; i < NITER; ++i) {
        const int t4 = cbase + 4 * (tid + i * THREADS);
        // v[t4..t4+4] from two aligned float4s (window select is compile-time)
        float4 lo = __ldg(reinterpret_cast<const float4*>(v_row + t4 - O));
        float4 hi = __ldg(reinterpret_cast<const float4*>(v_row + t4 - O + 4));
        float w[8] = {lo.x, lo.y, lo.z, lo.w, hi.x, hi.y, hi.z, hi.w};
        float4 r4 = __ldg(reinterpret_cast<const float4*>(r_row + t4));

        float d0 = r4.x + GAMMA * w[O + 1] - w[O];
        float d1 = r4.y + GAMMA * w[O + 2] - w[O + 1];
        float d2 = r4.z + GAMMA * w[O + 3] - w[O + 2];
        float d3 = r4.w + GAMMA * w[O + 4] - w[O + 3];

        // reverse scan within quad (zero carry)
        float q3 = d3;
        float q2 = fmaf(C1, q3, d2);
        float q1 = fmaf(C1, q2, d1);
        float q0 = fmaf(C1, q1, d0);

        // warp reverse scan of quad summaries, multiplier C4 per step
        float S = q0, a2;
        a2 = __shfl_down_sync(0xffffffffu, S, 1);  if (lane < 31) S = fmaf(C4,  a2, S);
        a2 = __shfl_down_sync(0xffffffffu, S, 2);  if (lane < 30) S = fmaf(C8,  a2, S);
        a2 = __shfl_down_sync(0xffffffffu, S, 4);  if (lane < 28) S = fmaf(C16, a2, S);
        a2 = __shfl_down_sync(0xffffffffu, S, 8);  if (lane < 24) S = fmaf(C32, a2, S);
        a2 = __shfl_down_sync(0xffffffffu, S, 16); if (lane < 16) S = fmaf(C64, a2, S);

        float E = __shfl_down_sync(0xffffffffu, S, 1);   // carry into this quad
        if (lane == 31) E = 0.0f;

        s0[i] = fmaf(C4, E, q0);
        s1[i] = fmaf(C3, E, q1);
        s2[i] = fmaf(C2, E, q2);
        s3[i] = fmaf(C1, E, q3);
        if (lane == 0) sum[i * 16 + wid] = S;    // 128-elem chunk summary
    }

    // ── Halo pass: 512 scalar elements beyond the chunk (guarded at row end).
    {
        const int t = cbase + CHUNK + tid;
        const bool inb = (t < T_CONST);
        float vt  = inb ? __ldg(v_row + t)     : 0.0f;
        float vt1 = inb ? __ldg(v_row + t + 1) : 0.0f;
        float rt  = inb ? __ldg(r_row + t)     : 0.0f;
        float a = inb ? (rt + GAMMA * vt1 - vt) : 0.0f;
        float a2;
        a2 = __shfl_down_sync(0xffffffffu, a, 1);  if (lane < 31) a = fmaf(C1,  a2, a);
        a2 = __shfl_down_sync(0xffffffffu, a, 2);  if (lane < 30) a = fmaf(C2,  a2, a);
        a2 = __shfl_down_sync(0xffffffffu, a, 4);  if (lane < 28) a = fmaf(C4,  a2, a);
        a2 = __shfl_down_sync(0xffffffffu, a, 8);  if (lane < 24) a = fmaf(C8,  a2, a);
        a2 = __shfl_down_sync(0xffffffffu, a, 16); if (lane < 16) a = fmaf(C16, a2, a);
        if (lane == 0) sum[NMAIN + wid] = a;     // 32-elem halo chunk summary
    }
    __syncthreads();

    // ── Phase 2 (warp 0 only): scan 16 halo summaries (mult M32), then 32
    // main summaries (mult M128); fold halo total in analytically.
    if (wid == 0) {
        float A = (lane < NHALO) ? sum[NMAIN + lane] : 0.0f;
        float a2, k = M32;
        a2 = __shfl_down_sync(0xffffffffu, A, 1);  if (lane < 31) A = fmaf(k, a2, A); k *= k;
        a2 = __shfl_down_sync(0xffffffffu, A, 2);  if (lane < 30) A = fmaf(k, a2, A); k *= k;
        a2 = __shfl_down_sync(0xffffffffu, A, 4);  if (lane < 28) A = fmaf(k, a2, A); k *= k;
        a2 = __shfl_down_sync(0xffffffffu, A, 8);  if (lane < 24) A = fmaf(k, a2, A);
        float T1 = __shfl_sync(0xffffffffu, A, 0);

        // main scan (zero carry), uniform multiplier M128
        float S = sum[lane];
        k = M128;
        a2 = __shfl_down_sync(0xffffffffu, S, 1);  if (lane < 31) S = fmaf(k, a2, S); k *= k;
        a2 = __shfl_down_sync(0xffffffffu, S, 2);  if (lane < 30) S = fmaf(k, a2, S); k *= k;
        a2 = __shfl_down_sync(0xffffffffu, S, 4);  if (lane < 28) S = fmaf(k, a2, S); k *= k;
        a2 = __shfl_down_sync(0xffffffffu, S, 8);  if (lane < 24) S = fmaf(k, a2, S); k *= k;
        a2 = __shfl_down_sync(0xffffffffu, S, 16); if (lane < 16) S = fmaf(k, a2, S);

        // carry entering chunk c: G_{c+1} = S_{c+1} + M128^(31-c) * T1
        float Sn   = __shfl_down_sync(0xffffffffu, S, 1);
        float corr = powi_coef(M128, 31 - lane);
        csum[lane] = (lane == 31) ? T1 : fmaf(corr, T1, Sn);
    }
    __syncthreads();

    // ── Phase 3: apply carries, reload v (L1/L2-resident), vector stores.
    float m3 = powi_coef(COEF, 125 - 4 * lane);           // COEF^(125-4l)
    float m2 = m3 * C1, m1 = m2 * C1, m0 = m1 * C1;       // .. up to COEF^(128-4l)

    #pragma unroll
    for (int i = 0; i < NITER; ++i) {
        const int t4 = cbase + 4 * (tid + i * THREADS);
        const float carry = csum[i * 16 + wid];           // broadcast in warp
        float A0 = fmaf(m0, carry, s0[i]);
        float A1 = fmaf(m1, carry, s1[i]);
        float A2 = fmaf(m2, carry, s2[i]);
        float A3 = fmaf(m3, carry, s3[i]);

        float w0, w1, w2, w3;
        {
            float4 lo = __ldg(reinterpret_cast<const float4*>(v_row + t4 - O));
            if constexpr (O == 0) {
                w0 = lo.x; w1 = lo.y; w2 = lo.z; w3 = lo.w;
            } else {
                float4 hi = __ldg(reinterpret_cast<const float4*>(v_row + t4 - O + 4));
                float w[8] = {lo.x, lo.y, lo.z, lo.w, hi.x, hi.y, hi.z, hi.w};
                w0 = w[O]; w1 = w[O + 1]; w2 = w[O + 2]; w3 = w[O + 3];
            }
        }
        *reinterpret_cast<float4*>(arow + t4) = make_float4(A0, A1, A2, A3);
        *reinterpret_cast<float4*>(trow + t4) =
            make_float4(w0 + A0, w1 + A1, w2 + A2, w3 + A3);
    }
}

__global__ __launch_bounds__(THREADS, 4)
void gae_kernel(const float* __restrict__ rewards,
                const float* __restrict__ values,
                float* __restrict__ adv_out,
                float* __restrict__ tgt_out)
{
    __shared__ float sum[NMAIN + NHALO];   // 48 chunk summaries
    __shared__ float csum[NMAIN];          // carries for main chunks

    const int row   = blockIdx.x >> 1;
    const int half  = blockIdx.x & 1;
    const int cbase = half * CHUNK;

    const float* r_row = rewards + (size_t)row * T_CONST;
    const float* v_row = values  + (size_t)row * (T_CONST + 1);
    float* arow = adv_out + (size_t)row * T_CONST;
    float* trow = tgt_out + (size_t)row * T_CONST;

    // values row misalignment: O = (row*8193 + t) % 4 = row % 4 for 4|t.
    // Last row (4095) has O=3 -> max vector-touched index is exactly v[T].
    // Other rows may over-read <=3 floats into the next row: inside buffer.
    switch (row & 3) {
        case 0:  gae_body<0>(r_row, v_row, arow, trow, cbase, sum, csum); break;
        case 1:  gae_body<1>(r_row, v_row, arow, trow, cbase, sum, csum); break;
        case 2:  gae_body<2>(r_row, v_row, arow, trow, cbase, sum, csum); break;
        default: gae_body<3>(r_row, v_row, arow, trow, cbase, sum, csum); break;
    }
}

extern "C" void kernel_launch(void* const* d_in, const int* in_sizes, int n_in,
                              void* d_out, int out_size)
{
    const float* rewards = (const float*)d_in[0];   // [B, T]
    const float* values  = (const float*)d_in[1];   // [B, T+1]
    float* adv = (float*)d_out;                     // [B, T]
    float* tgt = adv + (size_t)B_CONST * T_CONST;   // [B, T]

    gae_kernel<<<B_CONST * 2, THREADS>>>(rewards, values, adv, tgt);
}